// round 15
// baseline (speedup 1.0000x reference)
#include <cuda_runtime.h>
#include <stdint.h>

#define LL 4
#define BB 4
#define HH 4096
#define NKVH 8
#define HD 128
#define SS 1024

static const long long TEN     = (long long)LL * BB * NKVH * (SS + 1) * HD; // 16,793,600
static const long long TEN_F4  = TEN / 4;                                   // 4,198,400
static const long long PAST_F4 = 1LL << 22;   // per-tensor past float4 count
static const long long TOT_F4  = 1LL << 23;   // both tensors

#define PROJ_BLOCKS 128
#define COPY_BLOCKS 168
#define NBLOCKS     (PROJ_BLOCKS + COPY_BLOCKS)   // 296 = 2/SM, one wave
#define NTHREADS    512

// Copy split: copy blocks grid-stride over the first 7/8 (896 x 8192-float4
// chunks); each proj block copies one 8192-float4 tail chunk after its GEMV.
#define CHUNK_F4    8192
#define COPY_MAIN_F4 (896LL * CHUNK_F4)       // 7,340,032

// ---- packed f32x2 helpers (sm_100+; ptxas won't auto-fuse these) ----------
__device__ __forceinline__ void fma2(unsigned long long& acc,
                                     unsigned long long ab,
                                     unsigned long long hv) {
    asm("fma.rn.f32x2 %0, %1, %2, %0;" : "+l"(acc) : "l"(ab), "l"(hv));
}
__device__ __forceinline__ unsigned long long pack2(float w) {
    unsigned long long r;
    asm("mov.b64 %0, {%1, %1};" : "=l"(r) : "f"(w));
    return r;
}
__device__ __forceinline__ void unpack2(unsigned long long v, float& lo, float& hi) {
    asm("mov.b64 {%0, %1}, %2;" : "=f"(lo), "=f"(hi) : "l"(v));
}

// ---------------------------------------------------------------------------
// Fused kernel, fully static partition. R13 schedule + streaming cache hints
// on the copy traffic ONLY (the single unconfounded change this round).
//  Blocks [0,128):   GEMV (k,v) + RoPE, then copy ONE tail chunk (128KB).
//  Blocks [128,296): free-running strided copy over the first 7/8 of past_kv.
// ---------------------------------------------------------------------------
__global__ void __launch_bounds__(NTHREADS, 2)
kv_fused_kernel(const int* __restrict__ token_id,
                const int* __restrict__ pos_id,
                const float* __restrict__ embed_w,
                const float* __restrict__ wk,
                const float* __restrict__ wv,
                const float* __restrict__ inv_freq,
                const float4* __restrict__ past_k,
                const float4* __restrict__ past_v,
                float* __restrict__ out) {
    const int tid = threadIdx.x;
    float4* __restrict__ o4 = reinterpret_cast<float4*>(out);

    if (blockIdx.x >= PROJ_BLOCKS) {
        // ---------------- copy path (first 7/8) ----------------
        const long long CT = (long long)COPY_BLOCKS * NTHREADS;   // 86016
        long long ctid = (long long)(blockIdx.x - PROJ_BLOCKS) * NTHREADS + tid;

        long long idx = ctid;
        for (; idx + 7 * CT < COPY_MAIN_F4; idx += 8 * CT) {
            float4 v[8];
            long long j[8];
            long long t[8];
            #pragma unroll
            for (int u = 0; u < 8; u++) {
                long long i = idx + u * CT;
                t[u] = i >> 22;
                j[u] = i & (PAST_F4 - 1);
                v[u] = __ldcs(t[u] ? &past_v[j[u]] : &past_k[j[u]]);
            }
            #pragma unroll
            for (int u = 0; u < 8; u++)
                __stcs(&o4[t[u] * TEN_F4 + j[u] + ((j[u] >> 15) << 5)], v[u]);
        }
        for (; idx < COPY_MAIN_F4; idx += CT) {
            long long t = idx >> 22;
            long long j = idx & (PAST_F4 - 1);
            float4 v = __ldcs(t ? &past_v[j] : &past_k[j]);
            __stcs(&o4[t * TEN_F4 + j + ((j >> 15) << 5)], v);
        }
        return;
    }

    // ---------------- projection phase ----------------
    extern __shared__ float4 sh[];  // 64KB, batch-interleaved hidden
    {
        long long tk0 = token_id[0], tk1 = token_id[1];
        long long tk2 = token_id[2], tk3 = token_id[3];
        const float* e0 = embed_w + tk0 * HH;
        const float* e1 = embed_w + tk1 * HH;
        const float* e2 = embed_w + tk2 * HH;
        const float* e3 = embed_w + tk3 * HH;
        #pragma unroll
        for (int it = 0; it < 8; it++) {
            int e  = tid + it * NTHREADS;        // 0..4095
            int a  = e >> 10;
            int i  = e & 1023;
            int p0 = 4 * i + 2 * (a & 1);
            const float* ea = (a < 2) ? e0 : e2;
            const float* eb = (a < 2) ? e1 : e3;
            float2 x = *reinterpret_cast<const float2*>(ea + p0);
            float2 y = *reinterpret_cast<const float2*>(eb + p0);
            sh[e] = make_float4(x.x, y.x, x.y, y.y);
        }
    }
    __syncthreads();

    const int warp  = tid >> 5;
    const int lane  = tid & 31;
    const int gwarp = blockIdx.x * 16 + warp;   // 0..2047
    const int lkv   = gwarp >> 8;
    const int l     = lkv >> 1;
    const int kv    = lkv & 1;
    const int r0    = (gwarp & 255) * 4;

    const float* wbase = (kv == 0 ? wk : wv);
    const float4* wb4 = reinterpret_cast<const float4*>(
        wbase + ((long long)l * (NKVH * HD) + r0) * HH);
    const ulonglong2* shp = reinterpret_cast<const ulonglong2*>(sh);

    unsigned long long acc01[4], acc23[4];
    #pragma unroll
    for (int r = 0; r < 4; r++) { acc01[r] = 0ull; acc23[r] = 0ull; }

    #pragma unroll 2
    for (int i = lane; i < HH / 4; i += 32) {
        float4 w0 = wb4[i];
        float4 w1 = wb4[i + 1024];
        float4 w2 = wb4[i + 2048];
        float4 w3 = wb4[i + 3072];
        ulonglong2 a01 = shp[i];
        ulonglong2 b01 = shp[i + 1024];
        ulonglong2 a23 = shp[i + 2048];
        ulonglong2 b23 = shp[i + 3072];

        const float4 wv_[4] = {w0, w1, w2, w3};
        #pragma unroll
        for (int r = 0; r < 4; r++) {
            unsigned long long p;
            p = pack2(wv_[r].x); fma2(acc01[r], p, a01.x); fma2(acc23[r], p, a23.x);
            p = pack2(wv_[r].y); fma2(acc01[r], p, a01.y); fma2(acc23[r], p, a23.y);
            p = pack2(wv_[r].z); fma2(acc01[r], p, b01.x); fma2(acc23[r], p, b23.x);
            p = pack2(wv_[r].w); fma2(acc01[r], p, b01.y); fma2(acc23[r], p, b23.y);
        }
    }

    float acc[4][BB];
    #pragma unroll
    for (int r = 0; r < 4; r++) {
        unpack2(acc01[r], acc[r][0], acc[r][1]);
        unpack2(acc23[r], acc[r][2], acc[r][3]);
    }

    #pragma unroll
    for (int off = 16; off > 0; off >>= 1)
        #pragma unroll
        for (int r = 0; r < 4; r++)
            #pragma unroll
            for (int b = 0; b < BB; b++)
                acc[r][b] += __shfl_down_sync(0xffffffffu, acc[r][b], off);

    if (lane == 0) {
        const int n  = r0 >> 7;
        const int m0 = (r0 & 127) >> 1;
        const long long base_t = (kv == 0) ? 0LL : TEN;
        #pragma unroll
        for (int p = 0; p < 2; p++) {
            const float f = inv_freq[l * (HD / 2) + m0 + p];
            #pragma unroll
            for (int b = 0; b < BB; b++) {
                float e = acc[2 * p][b];
                float o = acc[2 * p + 1][b];
                float re = e, ro = o;
                if (kv == 0) {
                    float ang = (float)pos_id[b] * f;
                    float s, c;
                    sincosf(ang, &s, &c);
                    re = e * c - o * s;
                    ro = e * s + o * c;
                }
                long long dst = base_t +
                    ((((long long)l * BB + b) * NKVH + n) * (SS + 1) + SS) * HD
                    + 2 * (m0 + p);
                out[dst]     = re;
                out[dst + 1] = ro;
            }
        }
    }

    // ---------------- static tail chunk copy (no sync needed) ----------------
    {
        long long base = COPY_MAIN_F4 + (long long)blockIdx.x * CHUNK_F4;
        long long t    = base >> 22;                 // constant within chunk
        long long j0   = base & (PAST_F4 - 1);
        const float4* __restrict__ src = (t ? past_v : past_k) + j0;
        float4* __restrict__ dst = o4 + t * TEN_F4 + j0 + ((j0 >> 15) << 5);

        #pragma unroll
        for (int half = 0; half < 2; half++) {
            float4 v[8];
            int b0 = half * 8 * NTHREADS + tid;
            #pragma unroll
            for (int u = 0; u < 8; u++)
                v[u] = __ldcs(&src[b0 + u * NTHREADS]);
            #pragma unroll
            for (int u = 0; u < 8; u++)
                __stcs(&dst[b0 + u * NTHREADS], v[u]);
        }
    }
}

extern "C" void kernel_launch(void* const* d_in, const int* in_sizes, int n_in,
                              void* d_out, int out_size) {
    const int*   token_id = (const int*)d_in[0];
    const int*   pos_id   = (const int*)d_in[1];
    const float* embed_w  = (const float*)d_in[2];
    // d_in[3] = wq (unused: q never escapes the reference)
    const float* wk       = (const float*)d_in[4];
    const float* wv       = (const float*)d_in[5];
    const float* inv_freq = (const float*)d_in[6];
    const float* past_k   = (const float*)d_in[7];
    const float* past_v   = (const float*)d_in[8];
    float*       out      = (float*)d_out;

    cudaFuncSetAttribute(kv_fused_kernel,
                         cudaFuncAttributeMaxDynamicSharedMemorySize, 65536);

    kv_fused_kernel<<<NBLOCKS, NTHREADS, 65536>>>(
        token_id, pos_id, embed_w, wk, wv, inv_freq,
        (const float4*)past_k, (const float4*)past_v, out);
}

// round 16
// speedup vs baseline: 1.0337x; 1.0337x over previous
#include <cuda_runtime.h>
#include <stdint.h>

#define LL 4
#define BB 4
#define HH 4096
#define NKVH 8
#define HD 128
#define SS 1024

static const long long TEN     = (long long)LL * BB * NKVH * (SS + 1) * HD; // 16,793,600
static const long long TEN_F4  = TEN / 4;                                   // 4,198,400
static const long long PAST_F4 = 1LL << 22;   // per-tensor past float4 count
static const long long TOT_F4  = 1LL << 23;   // both tensors

#define PROJ_BLOCKS 128
#define COPY_BLOCKS 168
#define NBLOCKS     (PROJ_BLOCKS + COPY_BLOCKS)   // 296 = 2/SM, one wave
#define NTHREADS    512

// Copy split: copy blocks grid-stride over the first 7/8 (896 x 8192-float4
// chunks); each proj block copies one 8192-float4 tail chunk after its GEMV.
#define CHUNK_F4    8192
#define COPY_MAIN_F4 (896LL * CHUNK_F4)       // 7,340,032

// ---- packed f32x2 helpers (sm_100+; ptxas won't auto-fuse these) ----------
__device__ __forceinline__ void fma2(unsigned long long& acc,
                                     unsigned long long ab,
                                     unsigned long long hv) {
    asm("fma.rn.f32x2 %0, %1, %2, %0;" : "+l"(acc) : "l"(ab), "l"(hv));
}
__device__ __forceinline__ unsigned long long pack2(float w) {
    unsigned long long r;
    asm("mov.b64 %0, {%1, %1};" : "=l"(r) : "f"(w));
    return r;
}
__device__ __forceinline__ void unpack2(unsigned long long v, float& lo, float& hi) {
    asm("mov.b64 {%0, %1}, %2;" : "=f"(lo), "=f"(hi) : "l"(v));
}

// ---------------------------------------------------------------------------
// Fused kernel, fully static partition. (Final form — best of 14 benched
// builds: fusion + dead-code traffic elimination + FMA2 + grid-strided copy
// with 8-deep batching + static tail balancing + default cache policy.)
//  Blocks [0,128):   GEMV (k,v) + RoPE, then copy ONE tail chunk (128KB).
//  Blocks [128,296): free-running strided copy over the first 7/8 of past_kv.
// ---------------------------------------------------------------------------
__global__ void __launch_bounds__(NTHREADS, 2)
kv_fused_kernel(const int* __restrict__ token_id,
                const int* __restrict__ pos_id,
                const float* __restrict__ embed_w,
                const float* __restrict__ wk,
                const float* __restrict__ wv,
                const float* __restrict__ inv_freq,
                const float4* __restrict__ past_k,
                const float4* __restrict__ past_v,
                float* __restrict__ out) {
    const int tid = threadIdx.x;
    float4* __restrict__ o4 = reinterpret_cast<float4*>(out);

    if (blockIdx.x >= PROJ_BLOCKS) {
        // ---------------- copy path (first 7/8) ----------------
        const long long CT = (long long)COPY_BLOCKS * NTHREADS;   // 86016
        long long ctid = (long long)(blockIdx.x - PROJ_BLOCKS) * NTHREADS + tid;

        long long idx = ctid;
        for (; idx + 7 * CT < COPY_MAIN_F4; idx += 8 * CT) {
            float4 v[8];
            long long j[8];
            long long t[8];
            #pragma unroll
            for (int u = 0; u < 8; u++) {
                long long i = idx + u * CT;
                t[u] = i >> 22;
                j[u] = i & (PAST_F4 - 1);
                v[u] = t[u] ? past_v[j[u]] : past_k[j[u]];
            }
            #pragma unroll
            for (int u = 0; u < 8; u++)
                o4[t[u] * TEN_F4 + j[u] + ((j[u] >> 15) << 5)] = v[u];
        }
        for (; idx < COPY_MAIN_F4; idx += CT) {
            long long t = idx >> 22;
            long long j = idx & (PAST_F4 - 1);
            float4 v = t ? past_v[j] : past_k[j];
            o4[t * TEN_F4 + j + ((j >> 15) << 5)] = v;
        }
        return;
    }

    // ---------------- projection phase ----------------
    extern __shared__ float4 sh[];  // 64KB, batch-interleaved hidden
    {
        long long tk0 = token_id[0], tk1 = token_id[1];
        long long tk2 = token_id[2], tk3 = token_id[3];
        const float* e0 = embed_w + tk0 * HH;
        const float* e1 = embed_w + tk1 * HH;
        const float* e2 = embed_w + tk2 * HH;
        const float* e3 = embed_w + tk3 * HH;
        #pragma unroll
        for (int it = 0; it < 8; it++) {
            int e  = tid + it * NTHREADS;        // 0..4095
            int a  = e >> 10;
            int i  = e & 1023;
            int p0 = 4 * i + 2 * (a & 1);
            const float* ea = (a < 2) ? e0 : e2;
            const float* eb = (a < 2) ? e1 : e3;
            float2 x = *reinterpret_cast<const float2*>(ea + p0);
            float2 y = *reinterpret_cast<const float2*>(eb + p0);
            sh[e] = make_float4(x.x, y.x, x.y, y.y);
        }
    }
    __syncthreads();

    const int warp  = tid >> 5;
    const int lane  = tid & 31;
    const int gwarp = blockIdx.x * 16 + warp;   // 0..2047
    const int lkv   = gwarp >> 8;
    const int l     = lkv >> 1;
    const int kv    = lkv & 1;
    const int r0    = (gwarp & 255) * 4;

    const float* wbase = (kv == 0 ? wk : wv);
    const float4* wb4 = reinterpret_cast<const float4*>(
        wbase + ((long long)l * (NKVH * HD) + r0) * HH);
    const ulonglong2* shp = reinterpret_cast<const ulonglong2*>(sh);

    unsigned long long acc01[4], acc23[4];
    #pragma unroll
    for (int r = 0; r < 4; r++) { acc01[r] = 0ull; acc23[r] = 0ull; }

    #pragma unroll 2
    for (int i = lane; i < HH / 4; i += 32) {
        float4 w0 = wb4[i];
        float4 w1 = wb4[i + 1024];
        float4 w2 = wb4[i + 2048];
        float4 w3 = wb4[i + 3072];
        ulonglong2 a01 = shp[i];
        ulonglong2 b01 = shp[i + 1024];
        ulonglong2 a23 = shp[i + 2048];
        ulonglong2 b23 = shp[i + 3072];

        const float4 wv_[4] = {w0, w1, w2, w3};
        #pragma unroll
        for (int r = 0; r < 4; r++) {
            unsigned long long p;
            p = pack2(wv_[r].x); fma2(acc01[r], p, a01.x); fma2(acc23[r], p, a23.x);
            p = pack2(wv_[r].y); fma2(acc01[r], p, a01.y); fma2(acc23[r], p, a23.y);
            p = pack2(wv_[r].z); fma2(acc01[r], p, b01.x); fma2(acc23[r], p, b23.x);
            p = pack2(wv_[r].w); fma2(acc01[r], p, b01.y); fma2(acc23[r], p, b23.y);
        }
    }

    float acc[4][BB];
    #pragma unroll
    for (int r = 0; r < 4; r++) {
        unpack2(acc01[r], acc[r][0], acc[r][1]);
        unpack2(acc23[r], acc[r][2], acc[r][3]);
    }

    #pragma unroll
    for (int off = 16; off > 0; off >>= 1)
        #pragma unroll
        for (int r = 0; r < 4; r++)
            #pragma unroll
            for (int b = 0; b < BB; b++)
                acc[r][b] += __shfl_down_sync(0xffffffffu, acc[r][b], off);

    if (lane == 0) {
        const int n  = r0 >> 7;
        const int m0 = (r0 & 127) >> 1;
        const long long base_t = (kv == 0) ? 0LL : TEN;
        #pragma unroll
        for (int p = 0; p < 2; p++) {
            const float f = inv_freq[l * (HD / 2) + m0 + p];
            #pragma unroll
            for (int b = 0; b < BB; b++) {
                float e = acc[2 * p][b];
                float o = acc[2 * p + 1][b];
                float re = e, ro = o;
                if (kv == 0) {
                    float ang = (float)pos_id[b] * f;
                    float s, c;
                    sincosf(ang, &s, &c);
                    re = e * c - o * s;
                    ro = e * s + o * c;
                }
                long long dst = base_t +
                    ((((long long)l * BB + b) * NKVH + n) * (SS + 1) + SS) * HD
                    + 2 * (m0 + p);
                out[dst]     = re;
                out[dst + 1] = ro;
            }
        }
    }

    // ---------------- static tail chunk copy (no sync needed) ----------------
    {
        long long base = COPY_MAIN_F4 + (long long)blockIdx.x * CHUNK_F4;
        long long t    = base >> 22;                 // constant within chunk
        long long j0   = base & (PAST_F4 - 1);
        const float4* __restrict__ src = (t ? past_v : past_k) + j0;
        float4* __restrict__ dst = o4 + t * TEN_F4 + j0 + ((j0 >> 15) << 5);

        #pragma unroll
        for (int half = 0; half < 2; half++) {
            float4 v[8];
            int b0 = half * 8 * NTHREADS + tid;
            #pragma unroll
            for (int u = 0; u < 8; u++)
                v[u] = src[b0 + u * NTHREADS];
            #pragma unroll
            for (int u = 0; u < 8; u++)
                dst[b0 + u * NTHREADS] = v[u];
        }
    }
}

extern "C" void kernel_launch(void* const* d_in, const int* in_sizes, int n_in,
                              void* d_out, int out_size) {
    const int*   token_id = (const int*)d_in[0];
    const int*   pos_id   = (const int*)d_in[1];
    const float* embed_w  = (const float*)d_in[2];
    // d_in[3] = wq (unused: q never escapes the reference)
    const float* wk       = (const float*)d_in[4];
    const float* wv       = (const float*)d_in[5];
    const float* inv_freq = (const float*)d_in[6];
    const float* past_k   = (const float*)d_in[7];
    const float* past_v   = (const float*)d_in[8];
    float*       out      = (float*)d_out;

    cudaFuncSetAttribute(kv_fused_kernel,
                         cudaFuncAttributeMaxDynamicSharedMemorySize, 65536);

    kv_fused_kernel<<<NBLOCKS, NTHREADS, 65536>>>(
        token_id, pos_id, embed_w, wk, wv, inv_freq,
        (const float4*)past_k, (const float4*)past_v, out);
}

// round 17
// speedup vs baseline: 1.0501x; 1.0159x over previous
#include <cuda_runtime.h>
#include <stdint.h>

#define LL 4
#define BB 4
#define HH 4096
#define NKVH 8
#define HD 128
#define SS 1024

static const long long TEN     = (long long)LL * BB * NKVH * (SS + 1) * HD; // 16,793,600
static const long long TEN_F4  = TEN / 4;                                   // 4,198,400
static const long long PAST_F4 = 1LL << 22;   // per-tensor past float4 count
static const long long TOT_F4  = 1LL << 23;   // both tensors

#define PROJ_BLOCKS 128
#define COPY_BLOCKS 168
#define NBLOCKS     (PROJ_BLOCKS + COPY_BLOCKS)   // 296 = 2/SM, one wave
#define NTHREADS    512

// Copy split: copy blocks grid-stride over the first 7/8 (896 x 8192-float4
// chunks); each proj block copies one 8192-float4 tail chunk after its GEMV.
#define CHUNK_F4    8192
#define COPY_MAIN_F4 (896LL * CHUNK_F4)       // 7,340,032

// ---- packed f32x2 helpers (sm_100+; ptxas won't auto-fuse these) ----------
__device__ __forceinline__ void fma2(unsigned long long& acc,
                                     unsigned long long ab,
                                     unsigned long long hv) {
    asm("fma.rn.f32x2 %0, %1, %2, %0;" : "+l"(acc) : "l"(ab), "l"(hv));
}
__device__ __forceinline__ unsigned long long pack2(float w) {
    unsigned long long r;
    asm("mov.b64 %0, {%1, %1};" : "=l"(r) : "f"(w));
    return r;
}
__device__ __forceinline__ void unpack2(unsigned long long v, float& lo, float& hi) {
    asm("mov.b64 {%0, %1}, %2;" : "=f"(lo), "=f"(hi) : "l"(v));
}

// ---------------------------------------------------------------------------
// Fused kernel, fully static partition. (Final form — best of 15 benched
// builds: fusion + dead-code traffic elimination (wq and the q projection are
// never computed: 402 MB of the reference's traffic) + FMA2 batch-packed GEMV
// + grid-strided copy with 8-deep batching + static tail balancing + default
// cache policy. Pinned at the mixed-R/W HBM ceiling: ~6.0 TB/s, 75% DRAM.)
//  Blocks [0,128):   GEMV (k,v) + RoPE, then copy ONE tail chunk (128KB).
//  Blocks [128,296): free-running strided copy over the first 7/8 of past_kv.
// ---------------------------------------------------------------------------
__global__ void __launch_bounds__(NTHREADS, 2)
kv_fused_kernel(const int* __restrict__ token_id,
                const int* __restrict__ pos_id,
                const float* __restrict__ embed_w,
                const float* __restrict__ wk,
                const float* __restrict__ wv,
                const float* __restrict__ inv_freq,
                const float4* __restrict__ past_k,
                const float4* __restrict__ past_v,
                float* __restrict__ out) {
    const int tid = threadIdx.x;
    float4* __restrict__ o4 = reinterpret_cast<float4*>(out);

    if (blockIdx.x >= PROJ_BLOCKS) {
        // ---------------- copy path (first 7/8) ----------------
        const long long CT = (long long)COPY_BLOCKS * NTHREADS;   // 86016
        long long ctid = (long long)(blockIdx.x - PROJ_BLOCKS) * NTHREADS + tid;

        long long idx = ctid;
        for (; idx + 7 * CT < COPY_MAIN_F4; idx += 8 * CT) {
            float4 v[8];
            long long j[8];
            long long t[8];
            #pragma unroll
            for (int u = 0; u < 8; u++) {
                long long i = idx + u * CT;
                t[u] = i >> 22;
                j[u] = i & (PAST_F4 - 1);
                v[u] = t[u] ? past_v[j[u]] : past_k[j[u]];
            }
            #pragma unroll
            for (int u = 0; u < 8; u++)
                o4[t[u] * TEN_F4 + j[u] + ((j[u] >> 15) << 5)] = v[u];
        }
        for (; idx < COPY_MAIN_F4; idx += CT) {
            long long t = idx >> 22;
            long long j = idx & (PAST_F4 - 1);
            float4 v = t ? past_v[j] : past_k[j];
            o4[t * TEN_F4 + j + ((j >> 15) << 5)] = v;
        }
        return;
    }

    // ---------------- projection phase ----------------
    extern __shared__ float4 sh[];  // 64KB, batch-interleaved hidden
    {
        long long tk0 = token_id[0], tk1 = token_id[1];
        long long tk2 = token_id[2], tk3 = token_id[3];
        const float* e0 = embed_w + tk0 * HH;
        const float* e1 = embed_w + tk1 * HH;
        const float* e2 = embed_w + tk2 * HH;
        const float* e3 = embed_w + tk3 * HH;
        #pragma unroll
        for (int it = 0; it < 8; it++) {
            int e  = tid + it * NTHREADS;        // 0..4095
            int a  = e >> 10;
            int i  = e & 1023;
            int p0 = 4 * i + 2 * (a & 1);
            const float* ea = (a < 2) ? e0 : e2;
            const float* eb = (a < 2) ? e1 : e3;
            float2 x = *reinterpret_cast<const float2*>(ea + p0);
            float2 y = *reinterpret_cast<const float2*>(eb + p0);
            sh[e] = make_float4(x.x, y.x, x.y, y.y);
        }
    }
    __syncthreads();

    const int warp  = tid >> 5;
    const int lane  = tid & 31;
    const int gwarp = blockIdx.x * 16 + warp;   // 0..2047
    const int lkv   = gwarp >> 8;
    const int l     = lkv >> 1;
    const int kv    = lkv & 1;
    const int r0    = (gwarp & 255) * 4;

    const float* wbase = (kv == 0 ? wk : wv);
    const float4* wb4 = reinterpret_cast<const float4*>(
        wbase + ((long long)l * (NKVH * HD) + r0) * HH);
    const ulonglong2* shp = reinterpret_cast<const ulonglong2*>(sh);

    unsigned long long acc01[4], acc23[4];
    #pragma unroll
    for (int r = 0; r < 4; r++) { acc01[r] = 0ull; acc23[r] = 0ull; }

    #pragma unroll 2
    for (int i = lane; i < HH / 4; i += 32) {
        float4 w0 = wb4[i];
        float4 w1 = wb4[i + 1024];
        float4 w2 = wb4[i + 2048];
        float4 w3 = wb4[i + 3072];
        ulonglong2 a01 = shp[i];
        ulonglong2 b01 = shp[i + 1024];
        ulonglong2 a23 = shp[i + 2048];
        ulonglong2 b23 = shp[i + 3072];

        const float4 wv_[4] = {w0, w1, w2, w3};
        #pragma unroll
        for (int r = 0; r < 4; r++) {
            unsigned long long p;
            p = pack2(wv_[r].x); fma2(acc01[r], p, a01.x); fma2(acc23[r], p, a23.x);
            p = pack2(wv_[r].y); fma2(acc01[r], p, a01.y); fma2(acc23[r], p, a23.y);
            p = pack2(wv_[r].z); fma2(acc01[r], p, b01.x); fma2(acc23[r], p, b23.x);
            p = pack2(wv_[r].w); fma2(acc01[r], p, b01.y); fma2(acc23[r], p, b23.y);
        }
    }

    float acc[4][BB];
    #pragma unroll
    for (int r = 0; r < 4; r++) {
        unpack2(acc01[r], acc[r][0], acc[r][1]);
        unpack2(acc23[r], acc[r][2], acc[r][3]);
    }

    #pragma unroll
    for (int off = 16; off > 0; off >>= 1)
        #pragma unroll
        for (int r = 0; r < 4; r++)
            #pragma unroll
            for (int b = 0; b < BB; b++)
                acc[r][b] += __shfl_down_sync(0xffffffffu, acc[r][b], off);

    if (lane == 0) {
        const int n  = r0 >> 7;
        const int m0 = (r0 & 127) >> 1;
        const long long base_t = (kv == 0) ? 0LL : TEN;
        #pragma unroll
        for (int p = 0; p < 2; p++) {
            const float f = inv_freq[l * (HD / 2) + m0 + p];
            #pragma unroll
            for (int b = 0; b < BB; b++) {
                float e = acc[2 * p][b];
                float o = acc[2 * p + 1][b];
                float re = e, ro = o;
                if (kv == 0) {
                    float ang = (float)pos_id[b] * f;
                    float s, c;
                    sincosf(ang, &s, &c);
                    re = e * c - o * s;
                    ro = e * s + o * c;
                }
                long long dst = base_t +
                    ((((long long)l * BB + b) * NKVH + n) * (SS + 1) + SS) * HD
                    + 2 * (m0 + p);
                out[dst]     = re;
                out[dst + 1] = ro;
            }
        }
    }

    // ---------------- static tail chunk copy (no sync needed) ----------------
    {
        long long base = COPY_MAIN_F4 + (long long)blockIdx.x * CHUNK_F4;
        long long t    = base >> 22;                 // constant within chunk
        long long j0   = base & (PAST_F4 - 1);
        const float4* __restrict__ src = (t ? past_v : past_k) + j0;
        float4* __restrict__ dst = o4 + t * TEN_F4 + j0 + ((j0 >> 15) << 5);

        #pragma unroll
        for (int half = 0; half < 2; half++) {
            float4 v[8];
            int b0 = half * 8 * NTHREADS + tid;
            #pragma unroll
            for (int u = 0; u < 8; u++)
                v[u] = src[b0 + u * NTHREADS];
            #pragma unroll
            for (int u = 0; u < 8; u++)
                dst[b0 + u * NTHREADS] = v[u];
        }
    }
}

extern "C" void kernel_launch(void* const* d_in, const int* in_sizes, int n_in,
                              void* d_out, int out_size) {
    const int*   token_id = (const int*)d_in[0];
    const int*   pos_id   = (const int*)d_in[1];
    const float* embed_w  = (const float*)d_in[2];
    // d_in[3] = wq (unused: q never escapes the reference)
    const float* wk       = (const float*)d_in[4];
    const float* wv       = (const float*)d_in[5];
    const float* inv_freq = (const float*)d_in[6];
    const float* past_k   = (const float*)d_in[7];
    const float* past_v   = (const float*)d_in[8];
    float*       out      = (float*)d_out;

    cudaFuncSetAttribute(kv_fused_kernel,
                         cudaFuncAttributeMaxDynamicSharedMemorySize, 65536);

    kv_fused_kernel<<<NBLOCKS, NTHREADS, 65536>>>(
        token_id, pos_id, embed_w, wk, wv, inv_freq,
        (const float4*)past_k, (const float4*)past_v, out);
}